// round 2
// baseline (speedup 1.0000x reference)
#include <cuda_runtime.h>
#include <cstdint>

// Leaky RNN: x_t = 0.9*x_{t-1} + 0.1*(u@Win + tanh(x_{t-1})@Wrec + brec) + q_t
//            z_t = tanh(x_t)@Wout + bout
// T=1024, B=64, NIN=32, N=256, NOUT=16.
//
// 128 CTAs = 64 batches x 2 cluster ranks. Rank owns 128 columns of x.
// 256 threads: s=0 group (tid<128) consumes the LOCAL r-half (k in own rank's half),
// owns state x, does Win proj + prefetch + combine + sends. s=1 group (tid>=128)
// waits on an mbarrier for the PEER r-half (DSMEM st + remote release-arrive),
// computes the peer-half partial, and warp 8 computes the z output projection.
// All recurrent FMAs are packed fp32x2 (FFMA2). No barrier.cluster in the loop.

#define T_STEPS 1024
#define B_SZ    64
#define N_IN    32
#define N_HID   256
#define N_OUT   16

typedef unsigned long long ull;

__device__ __forceinline__ void ffma2(ull& acc, ull a, ull b) {
    asm("fma.rn.f32x2 %0, %1, %2, %0;" : "+l"(acc) : "l"(a), "l"(b));
}
__device__ __forceinline__ ull fadd2(ull a, ull b) {
    ull r; asm("add.rn.f32x2 %0, %1, %2;" : "=l"(r) : "l"(a), "l"(b)); return r;
}
__device__ __forceinline__ ull pack2(float lo, float hi) {
    ull r; asm("mov.b64 %0, {%1, %2};" : "=l"(r) : "f"(lo), "f"(hi)); return r;
}
__device__ __forceinline__ float hadd2(ull a) {
    float lo, hi; asm("mov.b64 {%0, %1}, %2;" : "=f"(lo), "=f"(hi) : "l"(a));
    return lo + hi;
}
__device__ __forceinline__ float ftanh(float x) {
    float e = __expf(2.0f * x);
    return 1.0f - __fdividef(2.0f, e + 1.0f);
}
__device__ __forceinline__ unsigned mapa32(unsigned laddr, unsigned peer) {
    unsigned r;
    asm volatile("mapa.shared::cluster.u32 %0, %1, %2;" : "=r"(r) : "r"(laddr), "r"(peer));
    return r;
}
__device__ __forceinline__ void st_remote_f32(unsigned addr, float v) {
    asm volatile("st.shared::cluster.f32 [%0], %1;" :: "r"(addr), "f"(v) : "memory");
}
__device__ __forceinline__ void arrive_remote(unsigned addr) {
    asm volatile("mbarrier.arrive.release.cluster.shared::cluster.b64 _, [%0];"
                 :: "r"(addr) : "memory");
}
__device__ __forceinline__ void mbar_wait_cluster(unsigned addr, unsigned parity) {
    unsigned done;
    do {
        asm volatile(
            "{\n\t.reg .pred P;\n\t"
            "mbarrier.try_wait.parity.acquire.cluster.shared::cta.b64 P, [%1], %2, 0x989680;\n\t"
            "selp.b32 %0, 1, 0, P;\n\t}"
            : "=r"(done) : "r"(addr), "r"(parity) : "memory");
    } while (!done);
}

#define CLUSTER_ARRIVE() asm volatile("barrier.cluster.arrive.aligned;" ::: "memory")
#define CLUSTER_WAIT()   asm volatile("barrier.cluster.wait.aligned;"   ::: "memory")

// 128 fp32 dot with register-stationary packed weights, r from smem (broadcast LDS.128)
__device__ __forceinline__ float dot128(const ull* w, const float* rbase) {
    const ulonglong2* rp = reinterpret_cast<const ulonglong2*>(rbase);
    ull a0 = 0, a1 = 0, a2 = 0, a3 = 0;
#pragma unroll
    for (int g = 0; g < 16; ++g) {
        ulonglong2 q0 = rp[2 * g];
        ulonglong2 q1 = rp[2 * g + 1];
        ffma2(a0, w[4 * g + 0], q0.x);
        ffma2(a1, w[4 * g + 1], q0.y);
        ffma2(a2, w[4 * g + 2], q1.x);
        ffma2(a3, w[4 * g + 3], q1.y);
    }
    return hadd2(fadd2(fadd2(a0, a1), fadd2(a2, a3)));
}

__global__ void __launch_bounds__(256, 1) __cluster_dims__(2, 1, 1)
rnn_kernel(const float* __restrict__ inputs,   // [T,B,NIN]
           const float* __restrict__ noise,    // [T,B,N]
           const float* __restrict__ x0,       // [B,N]
           const float* __restrict__ Win,      // [NIN,N]
           const float* __restrict__ Wrec,     // [N,N]
           const float* __restrict__ brec,     // [N]
           const float* __restrict__ Wout,     // [N,NOUT]
           const float* __restrict__ bout,     // [NOUT]
           float* __restrict__ outputs,        // [T,B,NOUT]
           float* __restrict__ states)         // [T,B,N]
{
    __shared__ __align__(16) float r2[2][N_HID];     // full r, double-buffered by parity
    __shared__ __align__(16) float sWinT[128][44];   // WinT[nl][i], pad 44 (16B-mult, cf)
    __shared__ __align__(16) float sWoutT[16][260];  // WoutT[o][n]
    __shared__ __align__(16) float sU[2][N_IN];      // u_t double-buffered
    __shared__ float sP[128];                        // peer-half partial sums
    __shared__ float sBout[16];
    __shared__ ull   mbar2[2];                       // peer-r arrival barriers (parity)

    const int tid = threadIdx.x;
    const int b   = blockIdx.x >> 1;
    const unsigned rank = blockIdx.x & 1u;
    const int sgrp = tid >> 7;              // 0: own-k / state owner; 1: peer-k
    const int nl   = tid & 127;             // local column
    const int gn   = (int)rank * 128 + nl;  // global column this thread accumulates
    const int khalf = sgrp ? (int)(rank ^ 1u) : (int)rank;  // k-half this thread multiplies

    // ---- register-stationary packed Wrec slice: w[j] = (Wrec[k][gn], Wrec[k+1][gn]) ----
    ull w[64];
#pragma unroll
    for (int j = 0; j < 64; ++j) {
        int k = khalf * 128 + 2 * j;
        w[j] = pack2(Wrec[k * N_HID + gn], Wrec[(k + 1) * N_HID + gn]);
    }

    // ---- smem staging ----
    for (int idx = tid; idx < N_IN * 128; idx += 256) {
        int i = idx >> 7, n2 = idx & 127;
        sWinT[n2][i] = Win[i * N_HID + (int)rank * 128 + n2];
    }
    for (int idx = tid; idx < N_HID * N_OUT; idx += 256) {
        int n2 = idx >> 4, o = idx & 15;
        sWoutT[o][n2] = Wout[idx];
    }
    if (tid < 16) sBout[tid] = bout[tid];
    if (tid < 32) sU[0][tid] = inputs[b * N_IN + tid];
    if (tid == 0) {
        asm volatile("mbarrier.init.shared.b64 [%0], %1;"
                     :: "r"((unsigned)__cvta_generic_to_shared(&mbar2[0])), "r"(128) : "memory");
        asm volatile("mbarrier.init.shared.b64 [%0], %1;"
                     :: "r"((unsigned)__cvta_generic_to_shared(&mbar2[1])), "r"(128) : "memory");
    }

    float x = 0.0f, qreg = 0.0f, ureg = 0.0f, brec_r = 0.0f;
    unsigned radd_r0 = 0, radd_m0 = 0;
    if (sgrp == 0) {
        x = x0[b * N_HID + gn];
        qreg = noise[b * N_HID + gn];
        brec_r = brec[gn];
        if (nl < 32) ureg = inputs[1 * (B_SZ * N_IN) + b * N_IN + nl];  // u_1
        unsigned l0 = (unsigned)__cvta_generic_to_shared(&r2[0][((int)rank << 7) + nl]);
        radd_r0 = mapa32(l0, rank ^ 1u);
        unsigned lm = (unsigned)__cvta_generic_to_shared(&mbar2[0]);
        radd_m0 = mapa32(lm, rank ^ 1u);
    }

    __syncthreads();          // mbar init + smem staging visible
    CLUSTER_ARRIVE(); CLUSTER_WAIT();   // peer mbar init visible before any remote op

    // ---- bootstrap: send r_{-1} = tanh(x0) halves, phase 0 ----
    if (sgrp == 0) {
        float r0 = ftanh(x);
        r2[0][((int)rank << 7) + nl] = r0;
        st_remote_f32(radd_r0, r0);
        arrive_remote(radd_m0);
    }
    __syncthreads();          // local r2[0] own half + sU visible to s=0 group

    int ph0 = 0, ph1 = 0;     // consumer parity per mbar (s=1 threads)

#pragma unroll 1
    for (int t = 0; t < T_STEPS; ++t) {
        const int p  = t & 1;
        const int nb = p ^ 1;

        float own_part = 0.0f, qnext = 0.0f;
        if (sgrp == 0) {
            // own-half recurrent partial (r produced locally last step)
            float sum = dot128(w, &r2[p][khalf << 7]);
            // input projection u_t @ Win[:, gn]
            const ulonglong2* up = reinterpret_cast<const ulonglong2*>(&sU[p][0]);
            const ulonglong2* wp = reinterpret_cast<const ulonglong2*>(&sWinT[nl][0]);
            ull c0 = 0, c1 = 0;
#pragma unroll
            for (int g = 0; g < 8; ++g) {
                ulonglong2 u2 = up[g];
                ulonglong2 w2 = wp[g];
                ffma2(c0, w2.x, u2.x);
                ffma2(c1, w2.y, u2.y);
            }
            own_part = sum + hadd2(fadd2(c0, c1)) + brec_r;
            // stage u_{t+1}, prefetch u_{t+2}
            if (nl < 32) {
                sU[nb][nl] = ureg;
                int tn = (t + 2 < T_STEPS) ? (t + 2) : (T_STEPS - 1);
                ureg = inputs[tn * (B_SZ * N_IN) + b * N_IN + nl];
            }
            int tq = (t + 1 < T_STEPS) ? (t + 1) : (T_STEPS - 1);
            qnext = noise[tq * (B_SZ * N_HID) + b * N_HID + gn];
        } else {
            // wait for peer r-half, then peer-half partial
            if (p == 0) { mbar_wait_cluster((unsigned)__cvta_generic_to_shared(&mbar2[0]), ph0); ph0 ^= 1; }
            else        { mbar_wait_cluster((unsigned)__cvta_generic_to_shared(&mbar2[1]), ph1); ph1 ^= 1; }
            sP[nl] = dot128(w, &r2[p][khalf << 7]);
        }

        __syncthreads();   // sP ready -> s=0 combine; r2[p] peer half visible CTA-wide

        if (sgrp == 0) {
            float tot = own_part + sP[nl];
            x = 0.9f * x + 0.1f * tot + qreg;
            qreg = qnext;
            float rt = ftanh(x);
            states[t * (B_SZ * N_HID) + b * N_HID + gn] = x;
            r2[nb][((int)rank << 7) + nl] = rt;
            st_remote_f32(radd_r0 + (unsigned)(nb * (N_HID * 4)), rt);
            arrive_remote(radd_m0 + (unsigned)(nb * 8));
        } else if (tid < 160 && t > 0) {
            // z_{t-1} = r_{t-1} @ Wout + bout ; r_{t-1} lives in r2[p] (full vector)
            int oo  = ((int)rank << 3) + ((tid - 128) >> 2);
            int seg = tid & 3;
            const ulonglong2* rz = reinterpret_cast<const ulonglong2*>(&r2[p][seg << 6]);
            const ulonglong2* wz = reinterpret_cast<const ulonglong2*>(&sWoutT[oo][seg << 6]);
            ull z0 = 0, z1 = 0;
#pragma unroll
            for (int g = 0; g < 16; ++g) {
                ulonglong2 rr = rz[g];
                ulonglong2 ww = wz[g];
                ffma2(z0, ww.x, rr.x);
                ffma2(z1, ww.y, rr.y);
            }
            float zz = hadd2(fadd2(z0, z1));
            zz += __shfl_xor_sync(0xffffffffu, zz, 1);
            zz += __shfl_xor_sync(0xffffffffu, zz, 2);
            if (seg == 0)
                outputs[(t - 1) * (B_SZ * N_OUT) + b * N_OUT + oo] = zz + sBout[oo];
        }

        __syncthreads();   // protect r2[nb]/sU[nb] writes vs next-iter reads, sP reuse
    }

    // ---- tail: z_{T-1} needs r_{T-1} (phase parity of t=T, i.e. 0) ----
    if (tid >= 128 && tid < 160) {
        mbar_wait_cluster((unsigned)__cvta_generic_to_shared(&mbar2[0]), ph0);
        int oo  = ((int)rank << 3) + ((tid - 128) >> 2);
        int seg = tid & 3;
        const ulonglong2* rz = reinterpret_cast<const ulonglong2*>(&r2[0][seg << 6]);
        const ulonglong2* wz = reinterpret_cast<const ulonglong2*>(&sWoutT[oo][seg << 6]);
        ull z0 = 0, z1 = 0;
#pragma unroll
        for (int g = 0; g < 16; ++g) {
            ulonglong2 rr = rz[g];
            ulonglong2 ww = wz[g];
            ffma2(z0, ww.x, rr.x);
            ffma2(z1, ww.y, rr.y);
        }
        float zz = hadd2(fadd2(z0, z1));
        zz += __shfl_xor_sync(0xffffffffu, zz, 1);
        zz += __shfl_xor_sync(0xffffffffu, zz, 2);
        if (seg == 0)
            outputs[(T_STEPS - 1) * (B_SZ * N_OUT) + b * N_OUT + oo] = zz + sBout[oo];
    }
}

extern "C" void kernel_launch(void* const* d_in, const int* in_sizes, int n_in,
                              void* d_out, int out_size) {
    const float* inputs = (const float*)d_in[0];
    const float* noise  = (const float*)d_in[1];
    const float* x0     = (const float*)d_in[2];
    const float* Win    = (const float*)d_in[3];
    const float* Wrec   = (const float*)d_in[4];
    const float* brec   = (const float*)d_in[5];
    const float* Wout   = (const float*)d_in[6];
    const float* bout   = (const float*)d_in[7];

    float* outputs = (float*)d_out;                                  // [T,B,NOUT]
    float* states  = (float*)d_out + (size_t)T_STEPS * B_SZ * N_OUT; // [T,B,N]

    rnn_kernel<<<dim3(B_SZ * 2), dim3(256)>>>(
        inputs, noise, x0, Win, Wrec, brec, Wout, bout, outputs, states);
}